// round 5
// baseline (speedup 1.0000x reference)
#include <cuda_runtime.h>
#include <math.h>

// Problem constants
// B=16, N=M=512, VS=2048, QS=1024, OS=2048, H=16, DH=128
#define ROWS      8192        // B * 512
#define TRANS_W   6144        // 3 * OS
#define OS_W      2048

// -------------------- scratch (device globals; no allocations allowed) -----
__device__ float g_vtrans[(size_t)ROWS * TRANS_W];
__device__ float g_qtrans[(size_t)ROWS * TRANS_W];
__device__ float g_vupd  [(size_t)ROWS * OS_W];
__device__ float g_qupd  [(size_t)ROWS * OS_W];

__device__ __forceinline__ unsigned f2tf32(float x) {
    unsigned r;
    asm("cvt.rna.tf32.f32 %0, %1;" : "=r"(r) : "f"(x));
    return r;
}

__device__ __forceinline__ void mma_tf32(float c[4], const unsigned a[4], const unsigned b[2]) {
    asm volatile(
        "mma.sync.aligned.m16n8k8.row.col.f32.tf32.tf32.f32 "
        "{%0,%1,%2,%3}, {%4,%5,%6,%7}, {%8,%9}, {%0,%1,%2,%3};\n"
        : "+f"(c[0]), "+f"(c[1]), "+f"(c[2]), "+f"(c[3])
        : "r"(a[0]), "r"(a[1]), "r"(a[2]), "r"(a[3]),
          "r"(b[0]), "r"(b[1]));
}

// ============================================================================
// TF32 tensor-core GEMM, CTA tile 128x256, 8 warps (2x4), warp tile 64x64.
// Dual-A "concat" support: rows come from A1 for k<K1, from A2 for K1<=k<K1+K2
// (both K1,K2 multiples of BK). C = relu(concat(A1,A2)@B + bias[col]) * mask.
// Double-buffered SMEM, one __syncthreads per K-chunk.
// ============================================================================
#define BM 128
#define BN 256
#define BK 16
#define AS_STRIDE 20
#define BS_STRIDE 264

__global__ void __launch_bounds__(256)
mma_gemm_kernel(const float* __restrict__ A1, int K1,
                const float* __restrict__ A2, int K2,
                const float* __restrict__ Bm,
                float* __restrict__ C,
                const float* __restrict__ bias, const float* __restrict__ mask,
                int N)
{
    __shared__ unsigned As[2][BM][AS_STRIDE];
    __shared__ unsigned Bs[2][BK][BS_STRIDE];

    const int tid  = threadIdx.x;
    const int lane = tid & 31;
    const int warp = tid >> 5;
    const int gid  = lane >> 2;        // 0..7
    const int tig  = lane & 3;         // 0..3
    const int wm = (warp >> 2) * 64;   // 0 or 64
    const int wn = (warp & 3) * 64;    // 0,64,128,192

    const int rowBase = blockIdx.y * BM;
    const int colBase = blockIdx.x * BN;

    // A tile 128x16: 512 float4; thread handles 2
    const int aR0 = tid >> 2;              // 0..63
    const int aK0 = (tid & 3) << 2;        // 0/4/8/12
    const int aR1 = aR0 + 64;
    // B tile 16x256: 1024 float4; thread handles 4
    const int bR0 = tid >> 6;              // 0..3 (then +4,+8,+12)
    const int bC0 = (tid & 63) << 2;       // 0..252

    const int K = K1 + K2;
    const int kChunks = K / BK;

    float acc[4][8][4];
#pragma unroll
    for (int i = 0; i < 4; i++)
#pragma unroll
        for (int j = 0; j < 8; j++)
#pragma unroll
            for (int r = 0; r < 4; r++) acc[i][j][r] = 0.0f;

    const float* Bp = Bm + (size_t)bR0 * N + colBase + bC0;

    // ---- prologue: prefetch chunk 0 ----
    float4 ra0, ra1, rb[4];
    {
        const float* a_src = A1; int kloc = 0, kd = K1;
        if (K1 == 0) { a_src = A2; kd = K2; }
        ra0 = *(const float4*)(a_src + (size_t)(rowBase + aR0) * kd + kloc + aK0);
        ra1 = *(const float4*)(a_src + (size_t)(rowBase + aR1) * kd + kloc + aK0);
#pragma unroll
        for (int i = 0; i < 4; i++)
            rb[i] = *(const float4*)(Bp + (size_t)(i * 4) * N);
    }

    for (int ck = 0; ck < kChunks; ck++) {
        const int cur = ck & 1;

        // store prefetched chunk -> stage cur
        {
            uint4 u0 = { f2tf32(ra0.x), f2tf32(ra0.y), f2tf32(ra0.z), f2tf32(ra0.w) };
            uint4 u1 = { f2tf32(ra1.x), f2tf32(ra1.y), f2tf32(ra1.z), f2tf32(ra1.w) };
            As[cur][aR0][aK0 + 0] = u0.x; As[cur][aR0][aK0 + 1] = u0.y;
            As[cur][aR0][aK0 + 2] = u0.z; As[cur][aR0][aK0 + 3] = u0.w;
            As[cur][aR1][aK0 + 0] = u1.x; As[cur][aR1][aK0 + 1] = u1.y;
            As[cur][aR1][aK0 + 2] = u1.z; As[cur][aR1][aK0 + 3] = u1.w;
#pragma unroll
            for (int i = 0; i < 4; i++) {
                Bs[cur][bR0 + i * 4][bC0 + 0] = f2tf32(rb[i].x);
                Bs[cur][bR0 + i * 4][bC0 + 1] = f2tf32(rb[i].y);
                Bs[cur][bR0 + i * 4][bC0 + 2] = f2tf32(rb[i].z);
                Bs[cur][bR0 + i * 4][bC0 + 3] = f2tf32(rb[i].w);
            }
        }
        __syncthreads();

        // prefetch next chunk
        if (ck + 1 < kChunks) {
            const int k0n = (ck + 1) * BK;
            const float* a_src; int kloc, kd;
            if (k0n < K1) { a_src = A1; kloc = k0n; kd = K1; }
            else          { a_src = A2; kloc = k0n - K1; kd = K2; }
            ra0 = *(const float4*)(a_src + (size_t)(rowBase + aR0) * kd + kloc + aK0);
            ra1 = *(const float4*)(a_src + (size_t)(rowBase + aR1) * kd + kloc + aK0);
            const float* bnext = Bp + (size_t)(ck + 1) * BK * N;
#pragma unroll
            for (int i = 0; i < 4; i++)
                rb[i] = *(const float4*)(bnext + (size_t)(i * 4) * N);
        }

        // compute: two k8 steps, 32 MMAs each
#pragma unroll
        for (int ks = 0; ks < 2; ks++) {
            const int kk = ks * 8 + tig;
            unsigned afr[4][4];
#pragma unroll
            for (int mt = 0; mt < 4; mt++) {
                const int r = wm + mt * 16 + gid;
                afr[mt][0] = As[cur][r][kk];
                afr[mt][1] = As[cur][r + 8][kk];
                afr[mt][2] = As[cur][r][kk + 4];
                afr[mt][3] = As[cur][r + 8][kk + 4];
            }
            unsigned bfr[8][2];
#pragma unroll
            for (int nt = 0; nt < 8; nt++) {
                const int c = wn + nt * 8 + gid;
                bfr[nt][0] = Bs[cur][kk][c];
                bfr[nt][1] = Bs[cur][kk + 4][c];
            }
#pragma unroll
            for (int mt = 0; mt < 4; mt++)
#pragma unroll
                for (int nt = 0; nt < 8; nt++)
                    mma_tf32(acc[mt][nt], afr[mt], bfr[nt]);
        }
        // next-iter store targets the other stage; safe with single sync
    }

    // ---- epilogue: relu(x + bias[col]) * mask[row] ----
#pragma unroll
    for (int mt = 0; mt < 4; mt++) {
        const int r0 = rowBase + wm + mt * 16 + gid;
        const int r1 = r0 + 8;
        const float m0 = mask ? mask[r0] : 1.0f;
        const float m1 = mask ? mask[r1] : 1.0f;
#pragma unroll
        for (int nt = 0; nt < 8; nt++) {
            const int c = colBase + wn + nt * 8 + (tig << 1);
            const float b0 = bias[c], b1 = bias[c + 1];
            float2 v0, v1;
            v0.x = fmaxf(acc[mt][nt][0] + b0, 0.0f) * m0;
            v0.y = fmaxf(acc[mt][nt][1] + b1, 0.0f) * m0;
            v1.x = fmaxf(acc[mt][nt][2] + b0, 0.0f) * m1;
            v1.y = fmaxf(acc[mt][nt][3] + b1, 0.0f) * m1;
            *(float2*)(C + (size_t)r0 * N + c) = v0;
            *(float2*)(C + (size_t)r1 * N + c) = v1;
        }
    }
}

// ============================================================================
// TF32 tensor-core flash attention (unchanged from R4, passing).
// ============================================================================
struct AttnSmem2 {
    unsigned Qs[128][132];
    unsigned Ks[64][132];
    unsigned Vs[64][136];
    unsigned Ps[128][68];
    float    Mk[64];
};

__global__ void __launch_bounds__(256)
attn_mma_kernel(const float* __restrict__ Tq, const float* __restrict__ Tk,
                const float* __restrict__ maskK, float* __restrict__ out)
{
    extern __shared__ char smem_raw[];
    AttnSmem2& sm = *reinterpret_cast<AttnSmem2*>(smem_raw);

    const int b  = blockIdx.z;
    const int h  = blockIdx.y;
    const int qt = blockIdx.x;
    const int tid  = threadIdx.x;
    const int lane = tid & 31;
    const int warp = tid >> 5;
    const int r0   = warp * 16;
    const int gid  = lane >> 2;
    const int tig  = lane & 3;
    const float SCALE = 0.08838834764831845f;

    const float* qbase = Tq + (size_t)(b * 512 + qt * 128) * 6144 + 2048 + h * 128;
#pragma unroll
    for (int it = 0; it < 16; it++) {
        int lin = it * 256 + tid;
        int r = lin >> 5, c4 = (lin & 31) << 2;
        float4 v = *(const float4*)(qbase + (size_t)r * 6144 + c4);
        uint4 u = { f2tf32(v.x), f2tf32(v.y), f2tf32(v.z), f2tf32(v.w) };
        *(uint4*)&sm.Qs[r][c4] = u;
    }

    float m_i[2] = { -INFINITY, -INFINITY };
    float l_i[2] = { 0.0f, 0.0f };
    float oacc[16][4];
#pragma unroll
    for (int nt = 0; nt < 16; nt++)
#pragma unroll
        for (int j = 0; j < 4; j++) oacc[nt][j] = 0.0f;

    const float* kbase = Tk + (size_t)b * 512 * 6144 + h * 128;
    const float* vbase = kbase + 4096;

    for (int kt = 0; kt < 8; kt++) {
        __syncthreads();
#pragma unroll
        for (int it = 0; it < 8; it++) {
            int lin = it * 256 + tid;
            int r = lin >> 5, c4 = (lin & 31) << 2;
            float4 kv = *(const float4*)(kbase + (size_t)(kt * 64 + r) * 6144 + c4);
            uint4 ku = { f2tf32(kv.x), f2tf32(kv.y), f2tf32(kv.z), f2tf32(kv.w) };
            *(uint4*)&sm.Ks[r][c4] = ku;
            float4 vv = *(const float4*)(vbase + (size_t)(kt * 64 + r) * 6144 + c4);
            uint4 vu = { f2tf32(vv.x), f2tf32(vv.y), f2tf32(vv.z), f2tf32(vv.w) };
            *(uint4*)&sm.Vs[r][c4] = vu;
        }
        if (tid < 64) sm.Mk[tid] = maskK[b * 512 + kt * 64 + tid];
        __syncthreads();

        float c[8][4];
#pragma unroll
        for (int nt = 0; nt < 8; nt++)
#pragma unroll
            for (int j = 0; j < 4; j++) c[nt][j] = 0.0f;

#pragma unroll
        for (int k8 = 0; k8 < 16; k8++) {
            const int kk = k8 * 8 + tig;
            unsigned a[4];
            a[0] = sm.Qs[r0 + gid][kk];
            a[1] = sm.Qs[r0 + gid + 8][kk];
            a[2] = sm.Qs[r0 + gid][kk + 4];
            a[3] = sm.Qs[r0 + gid + 8][kk + 4];
#pragma unroll
            for (int nt = 0; nt < 8; nt++) {
                unsigned bf[2];
                bf[0] = sm.Ks[nt * 8 + gid][kk];
                bf[1] = sm.Ks[nt * 8 + gid][kk + 4];
                mma_tf32(c[nt], a, bf);
            }
        }

#pragma unroll
        for (int nt = 0; nt < 8; nt++) {
            const int col = nt * 8 + tig * 2;
            const float k0m = sm.Mk[col];
            const float k1m = sm.Mk[col + 1];
            c[nt][0] = (k0m != 0.0f) ? c[nt][0] * SCALE : -INFINITY;
            c[nt][1] = (k1m != 0.0f) ? c[nt][1] * SCALE : -INFINITY;
            c[nt][2] = (k0m != 0.0f) ? c[nt][2] * SCALE : -INFINITY;
            c[nt][3] = (k1m != 0.0f) ? c[nt][3] * SCALE : -INFINITY;
        }

#pragma unroll
        for (int j = 0; j < 2; j++) {
            float tmax = -INFINITY;
#pragma unroll
            for (int nt = 0; nt < 8; nt++)
                tmax = fmaxf(tmax, fmaxf(c[nt][j * 2], c[nt][j * 2 + 1]));
            tmax = fmaxf(tmax, __shfl_xor_sync(0xffffffffu, tmax, 1));
            tmax = fmaxf(tmax, __shfl_xor_sync(0xffffffffu, tmax, 2));
            float mnew  = fmaxf(m_i[j], tmax);
            float msafe = (mnew == -INFINITY) ? 0.0f : mnew;
            float corr  = __expf(m_i[j] - msafe);
            float lsum = 0.0f;
            const int row = r0 + gid + j * 8;
#pragma unroll
            for (int nt = 0; nt < 8; nt++) {
                float p0 = __expf(c[nt][j * 2]     - msafe);
                float p1 = __expf(c[nt][j * 2 + 1] - msafe);
                lsum += p0 + p1;
                uint2 pu = { f2tf32(p0), f2tf32(p1) };
                *(uint2*)&sm.Ps[row][nt * 8 + tig * 2] = pu;
            }
            lsum += __shfl_xor_sync(0xffffffffu, lsum, 1);
            lsum += __shfl_xor_sync(0xffffffffu, lsum, 2);
            l_i[j] = l_i[j] * corr + lsum;
            m_i[j] = mnew;
#pragma unroll
            for (int nt = 0; nt < 16; nt++) {
                oacc[nt][j * 2]     *= corr;
                oacc[nt][j * 2 + 1] *= corr;
            }
        }
        __syncwarp();

#pragma unroll
        for (int k8 = 0; k8 < 8; k8++) {
            const int kk = k8 * 8 + tig;
            unsigned a[4];
            a[0] = sm.Ps[r0 + gid][kk];
            a[1] = sm.Ps[r0 + gid + 8][kk];
            a[2] = sm.Ps[r0 + gid][kk + 4];
            a[3] = sm.Ps[r0 + gid + 8][kk + 4];
#pragma unroll
            for (int nt = 0; nt < 16; nt++) {
                unsigned bf[2];
                bf[0] = sm.Vs[k8 * 8 + tig][nt * 8 + gid];
                bf[1] = sm.Vs[k8 * 8 + tig + 4][nt * 8 + gid];
                mma_tf32(oacc[nt], a, bf);
            }
        }
    }

#pragma unroll
    for (int j = 0; j < 2; j++) {
        const float inv = (l_i[j] > 0.0f) ? (1.0f / l_i[j]) : 0.0f;
        const size_t orow = (size_t)(b * 512 + qt * 128 + r0 + gid + j * 8);
        float* op = out + orow * 2048 + h * 128 + tig * 2;
#pragma unroll
        for (int nt = 0; nt < 16; nt++) {
            float2 o;
            o.x = oacc[nt][j * 2]     * inv;
            o.y = oacc[nt][j * 2 + 1] * inv;
            *(float2*)(op + nt * 8) = o;
        }
    }
}

// ============================================================================
extern "C" void kernel_launch(void* const* d_in, const int* in_sizes, int n_in,
                              void* d_out, int out_size)
{
    (void)in_sizes; (void)n_in; (void)out_size;
    const float* v     = (const float*)d_in[0];
    const float* q     = (const float*)d_in[1];
    const float* vmask = (const float*)d_in[2];
    const float* qmask = (const float*)d_in[3];
    const float* Wv    = (const float*)d_in[4];
    const float* bv    = (const float*)d_in[5];
    const float* Wq    = (const float*)d_in[6];
    const float* bq    = (const float*)d_in[7];
    const float* Wvo   = (const float*)d_in[8];
    const float* bvo   = (const float*)d_in[9];
    const float* Wqo   = (const float*)d_in[10];
    const float* bqo   = (const float*)d_in[11];

    float* out_v = (float*)d_out;
    float* out_q = out_v + (size_t)ROWS * OS_W;

    float *vtrans, *qtrans, *vupd, *qupd;
    cudaGetSymbolAddress((void**)&vtrans, g_vtrans);
    cudaGetSymbolAddress((void**)&qtrans, g_qtrans);
    cudaGetSymbolAddress((void**)&vupd,   g_vupd);
    cudaGetSymbolAddress((void**)&qupd,   g_qupd);

    cudaFuncSetAttribute(attn_mma_kernel, cudaFuncAttributeMaxDynamicSharedMemorySize,
                         (int)sizeof(AttnSmem2));

    dim3 blk(256);

    // 1) v_trans = relu(v @ Wv + bv) * v_mask     [8192,6144] K=2048
    mma_gemm_kernel<<<dim3(TRANS_W / BN, ROWS / BM), blk>>>(
        v, 2048, nullptr, 0, Wv, vtrans, bv, vmask, TRANS_W);
    // 2) q_trans = relu(q @ Wq + bq) * q_mask     [8192,6144] K=1024
    mma_gemm_kernel<<<dim3(TRANS_W / BN, ROWS / BM), blk>>>(
        q, 1024, nullptr, 0, Wq, qtrans, bq, qmask, TRANS_W);

    // 3) q2v attention -> v_update
    attn_mma_kernel<<<dim3(4, 16, 16), blk, sizeof(AttnSmem2)>>>(vtrans, qtrans, qmask, vupd);
    // 4) v2q attention -> q_update
    attn_mma_kernel<<<dim3(4, 16, 16), blk, sizeof(AttnSmem2)>>>(qtrans, vtrans, vmask, qupd);

    // 5) updated_v = relu([v | v_update] @ Wvo + bvo)   (fused concat GEMM)
    mma_gemm_kernel<<<dim3(OS_W / BN, ROWS / BM), blk>>>(
        v, 2048, vupd, 2048, Wvo, out_v, bvo, nullptr, OS_W);
    // 6) updated_q = relu([q | q_update] @ Wqo + bqo)
    mma_gemm_kernel<<<dim3(OS_W / BN, ROWS / BM), blk>>>(
        q, 1024, qupd, 2048, Wqo, out_q, bqo, nullptr, OS_W);
}

// round 6
// speedup vs baseline: 1.0622x; 1.0622x over previous
#include <cuda_runtime.h>
#include <math.h>

// Problem constants
// B=16, N=M=512, VS=2048, QS=1024, OS=2048, H=16, DH=128
#define ROWS      8192        // B * 512
#define TRANS_W   6144        // 3 * OS
#define OS_W      2048

// -------------------- scratch (device globals; no allocations allowed) -----
__device__ float g_vtrans[(size_t)ROWS * TRANS_W];
__device__ float g_qtrans[(size_t)ROWS * TRANS_W];
__device__ float g_vupd  [(size_t)ROWS * OS_W];
__device__ float g_qupd  [(size_t)ROWS * OS_W];

__device__ __forceinline__ unsigned f2tf32(float x) {
    unsigned r;
    asm("cvt.rna.tf32.f32 %0, %1;" : "=r"(r) : "f"(x));
    return r;
}

__device__ __forceinline__ void mma_tf32(float c[4], const unsigned a[4], const unsigned b[2]) {
    asm volatile(
        "mma.sync.aligned.m16n8k8.row.col.f32.tf32.tf32.f32 "
        "{%0,%1,%2,%3}, {%4,%5,%6,%7}, {%8,%9}, {%0,%1,%2,%3};\n"
        : "+f"(c[0]), "+f"(c[1]), "+f"(c[2]), "+f"(c[3])
        : "r"(a[0]), "r"(a[1]), "r"(a[2]), "r"(a[3]),
          "r"(b[0]), "r"(b[1]));
}

// ============================================================================
// TF32 tensor-core GEMM, R4 geometry (CTA 128x128, warp 64x32, BK=16,
// double-buffered, 2 CTAs/SM) + dual-A concat: rows come from A1 for k<K1,
// from A2 for K1<=k<K1+K2 (K1,K2 multiples of BK).
// C = relu(concat(A1,A2)@B + bias[col]) * mask[row]  (mask optional)
// ============================================================================
#define BM 128
#define BN 128
#define BK 16
#define AS_STRIDE 20
#define BS_STRIDE 136

__global__ void __launch_bounds__(256, 2)
mma_gemm_kernel(const float* __restrict__ A1, int K1,
                const float* __restrict__ A2, int K2,
                const float* __restrict__ Bm,
                float* __restrict__ C,
                const float* __restrict__ bias, const float* __restrict__ mask,
                int N)
{
    __shared__ unsigned As[2][BM][AS_STRIDE];
    __shared__ unsigned Bs[2][BK][BS_STRIDE];

    const int tid  = threadIdx.x;
    const int lane = tid & 31;
    const int warp = tid >> 5;
    const int wm = (warp >> 2) * 64;
    const int wn = (warp & 3) * 32;

    const int rowBase = blockIdx.y * BM;
    const int colBase = blockIdx.x * BN;

    const int aR0 = tid >> 2;              // 0..63
    const int aK0 = (tid & 3) << 2;        // 0/4/8/12
    const int aR1 = aR0 + 64;
    const int bR0 = tid >> 5;              // 0..7
    const int bC0 = (tid & 31) << 2;       // 0..124
    const int bR1 = bR0 + 8;

    const int K = K1 + K2;
    const int kChunks = K / BK;

    const float* Bp0 = Bm + (size_t)bR0 * N + colBase + bC0;
    const float* Bp1 = Bm + (size_t)bR1 * N + colBase + bC0;

    float acc[4][4][4];
#pragma unroll
    for (int i = 0; i < 4; i++)
#pragma unroll
        for (int j = 0; j < 4; j++)
#pragma unroll
            for (int r = 0; r < 4; r++) acc[i][j][r] = 0.0f;

    // ---- prologue: prefetch chunk 0 ----
    float4 ra0, ra1, rb0, rb1;
    {
        const float* a_src; int kd;
        if (K1 > 0) { a_src = A1; kd = K1; } else { a_src = A2; kd = K2; }
        ra0 = *(const float4*)(a_src + (size_t)(rowBase + aR0) * kd + aK0);
        ra1 = *(const float4*)(a_src + (size_t)(rowBase + aR1) * kd + aK0);
        rb0 = *(const float4*)Bp0;
        rb1 = *(const float4*)Bp1;
    }

    for (int ck = 0; ck < kChunks; ck++) {
        const int cur = ck & 1;

        As[cur][aR0][aK0 + 0] = f2tf32(ra0.x);
        As[cur][aR0][aK0 + 1] = f2tf32(ra0.y);
        As[cur][aR0][aK0 + 2] = f2tf32(ra0.z);
        As[cur][aR0][aK0 + 3] = f2tf32(ra0.w);
        As[cur][aR1][aK0 + 0] = f2tf32(ra1.x);
        As[cur][aR1][aK0 + 1] = f2tf32(ra1.y);
        As[cur][aR1][aK0 + 2] = f2tf32(ra1.z);
        As[cur][aR1][aK0 + 3] = f2tf32(ra1.w);
        Bs[cur][bR0][bC0 + 0] = f2tf32(rb0.x);
        Bs[cur][bR0][bC0 + 1] = f2tf32(rb0.y);
        Bs[cur][bR0][bC0 + 2] = f2tf32(rb0.z);
        Bs[cur][bR0][bC0 + 3] = f2tf32(rb0.w);
        Bs[cur][bR1][bC0 + 0] = f2tf32(rb1.x);
        Bs[cur][bR1][bC0 + 1] = f2tf32(rb1.y);
        Bs[cur][bR1][bC0 + 2] = f2tf32(rb1.z);
        Bs[cur][bR1][bC0 + 3] = f2tf32(rb1.w);
        __syncthreads();

        if (ck + 1 < kChunks) {
            const int k0n = (ck + 1) * BK;
            const float* a_src; int kloc, kd;
            if (k0n < K1) { a_src = A1; kloc = k0n;      kd = K1; }
            else          { a_src = A2; kloc = k0n - K1; kd = K2; }
            ra0 = *(const float4*)(a_src + (size_t)(rowBase + aR0) * kd + kloc + aK0);
            ra1 = *(const float4*)(a_src + (size_t)(rowBase + aR1) * kd + kloc + aK0);
            rb0 = *(const float4*)(Bp0 + (size_t)k0n * N);
            rb1 = *(const float4*)(Bp1 + (size_t)k0n * N);
        }

#pragma unroll
        for (int ks = 0; ks < 2; ks++) {
            const int k0 = ks * 8;
            unsigned afr[4][4];
#pragma unroll
            for (int mt = 0; mt < 4; mt++) {
                int r = wm + mt * 16 + (lane >> 2);
                int kk = k0 + (lane & 3);
                afr[mt][0] = As[cur][r][kk];
                afr[mt][1] = As[cur][r + 8][kk];
                afr[mt][2] = As[cur][r][kk + 4];
                afr[mt][3] = As[cur][r + 8][kk + 4];
            }
            unsigned bfr[4][2];
#pragma unroll
            for (int nt = 0; nt < 4; nt++) {
                int c = wn + nt * 8 + (lane >> 2);
                int kk = k0 + (lane & 3);
                bfr[nt][0] = Bs[cur][kk][c];
                bfr[nt][1] = Bs[cur][kk + 4][c];
            }
#pragma unroll
            for (int mt = 0; mt < 4; mt++)
#pragma unroll
                for (int nt = 0; nt < 4; nt++)
                    mma_tf32(acc[mt][nt], afr[mt], bfr[nt]);
        }
    }

    // ---- epilogue: relu(x + bias[col]) * mask[row] ----
#pragma unroll
    for (int mt = 0; mt < 4; mt++) {
        const int r0 = rowBase + wm + mt * 16 + (lane >> 2);
        const int r1 = r0 + 8;
        const float m0 = mask ? mask[r0] : 1.0f;
        const float m1 = mask ? mask[r1] : 1.0f;
#pragma unroll
        for (int nt = 0; nt < 4; nt++) {
            const int c = colBase + wn + nt * 8 + ((lane & 3) << 1);
            const float b0 = bias[c], b1 = bias[c + 1];
            float2 v0, v1;
            v0.x = fmaxf(acc[mt][nt][0] + b0, 0.0f) * m0;
            v0.y = fmaxf(acc[mt][nt][1] + b1, 0.0f) * m0;
            v1.x = fmaxf(acc[mt][nt][2] + b0, 0.0f) * m1;
            v1.y = fmaxf(acc[mt][nt][3] + b1, 0.0f) * m1;
            *(float2*)(C + (size_t)r0 * N + c) = v0;
            *(float2*)(C + (size_t)r1 * N + c) = v1;
        }
    }
}

// ============================================================================
// TF32 tensor-core flash attention (unchanged from R4, passing).
// ============================================================================
struct AttnSmem2 {
    unsigned Qs[128][132];
    unsigned Ks[64][132];
    unsigned Vs[64][136];
    unsigned Ps[128][68];
    float    Mk[64];
};

__global__ void __launch_bounds__(256)
attn_mma_kernel(const float* __restrict__ Tq, const float* __restrict__ Tk,
                const float* __restrict__ maskK, float* __restrict__ out)
{
    extern __shared__ char smem_raw[];
    AttnSmem2& sm = *reinterpret_cast<AttnSmem2*>(smem_raw);

    const int b  = blockIdx.z;
    const int h  = blockIdx.y;
    const int qt = blockIdx.x;
    const int tid  = threadIdx.x;
    const int lane = tid & 31;
    const int warp = tid >> 5;
    const int r0   = warp * 16;
    const int gid  = lane >> 2;
    const int tig  = lane & 3;
    const float SCALE = 0.08838834764831845f;

    const float* qbase = Tq + (size_t)(b * 512 + qt * 128) * 6144 + 2048 + h * 128;
#pragma unroll
    for (int it = 0; it < 16; it++) {
        int lin = it * 256 + tid;
        int r = lin >> 5, c4 = (lin & 31) << 2;
        float4 v = *(const float4*)(qbase + (size_t)r * 6144 + c4);
        uint4 u = { f2tf32(v.x), f2tf32(v.y), f2tf32(v.z), f2tf32(v.w) };
        *(uint4*)&sm.Qs[r][c4] = u;
    }

    float m_i[2] = { -INFINITY, -INFINITY };
    float l_i[2] = { 0.0f, 0.0f };
    float oacc[16][4];
#pragma unroll
    for (int nt = 0; nt < 16; nt++)
#pragma unroll
        for (int j = 0; j < 4; j++) oacc[nt][j] = 0.0f;

    const float* kbase = Tk + (size_t)b * 512 * 6144 + h * 128;
    const float* vbase = kbase + 4096;

    for (int kt = 0; kt < 8; kt++) {
        __syncthreads();
#pragma unroll
        for (int it = 0; it < 8; it++) {
            int lin = it * 256 + tid;
            int r = lin >> 5, c4 = (lin & 31) << 2;
            float4 kv = *(const float4*)(kbase + (size_t)(kt * 64 + r) * 6144 + c4);
            uint4 ku = { f2tf32(kv.x), f2tf32(kv.y), f2tf32(kv.z), f2tf32(kv.w) };
            *(uint4*)&sm.Ks[r][c4] = ku;
            float4 vv = *(const float4*)(vbase + (size_t)(kt * 64 + r) * 6144 + c4);
            uint4 vu = { f2tf32(vv.x), f2tf32(vv.y), f2tf32(vv.z), f2tf32(vv.w) };
            *(uint4*)&sm.Vs[r][c4] = vu;
        }
        if (tid < 64) sm.Mk[tid] = maskK[b * 512 + kt * 64 + tid];
        __syncthreads();

        float c[8][4];
#pragma unroll
        for (int nt = 0; nt < 8; nt++)
#pragma unroll
            for (int j = 0; j < 4; j++) c[nt][j] = 0.0f;

#pragma unroll
        for (int k8 = 0; k8 < 16; k8++) {
            const int kk = k8 * 8 + tig;
            unsigned a[4];
            a[0] = sm.Qs[r0 + gid][kk];
            a[1] = sm.Qs[r0 + gid + 8][kk];
            a[2] = sm.Qs[r0 + gid][kk + 4];
            a[3] = sm.Qs[r0 + gid + 8][kk + 4];
#pragma unroll
            for (int nt = 0; nt < 8; nt++) {
                unsigned bf[2];
                bf[0] = sm.Ks[nt * 8 + gid][kk];
                bf[1] = sm.Ks[nt * 8 + gid][kk + 4];
                mma_tf32(c[nt], a, bf);
            }
        }

#pragma unroll
        for (int nt = 0; nt < 8; nt++) {
            const int col = nt * 8 + tig * 2;
            const float k0m = sm.Mk[col];
            const float k1m = sm.Mk[col + 1];
            c[nt][0] = (k0m != 0.0f) ? c[nt][0] * SCALE : -INFINITY;
            c[nt][1] = (k1m != 0.0f) ? c[nt][1] * SCALE : -INFINITY;
            c[nt][2] = (k0m != 0.0f) ? c[nt][2] * SCALE : -INFINITY;
            c[nt][3] = (k1m != 0.0f) ? c[nt][3] * SCALE : -INFINITY;
        }

#pragma unroll
        for (int j = 0; j < 2; j++) {
            float tmax = -INFINITY;
#pragma unroll
            for (int nt = 0; nt < 8; nt++)
                tmax = fmaxf(tmax, fmaxf(c[nt][j * 2], c[nt][j * 2 + 1]));
            tmax = fmaxf(tmax, __shfl_xor_sync(0xffffffffu, tmax, 1));
            tmax = fmaxf(tmax, __shfl_xor_sync(0xffffffffu, tmax, 2));
            float mnew  = fmaxf(m_i[j], tmax);
            float msafe = (mnew == -INFINITY) ? 0.0f : mnew;
            float corr  = __expf(m_i[j] - msafe);
            float lsum = 0.0f;
            const int row = r0 + gid + j * 8;
#pragma unroll
            for (int nt = 0; nt < 8; nt++) {
                float p0 = __expf(c[nt][j * 2]     - msafe);
                float p1 = __expf(c[nt][j * 2 + 1] - msafe);
                lsum += p0 + p1;
                uint2 pu = { f2tf32(p0), f2tf32(p1) };
                *(uint2*)&sm.Ps[row][nt * 8 + tig * 2] = pu;
            }
            lsum += __shfl_xor_sync(0xffffffffu, lsum, 1);
            lsum += __shfl_xor_sync(0xffffffffu, lsum, 2);
            l_i[j] = l_i[j] * corr + lsum;
            m_i[j] = mnew;
#pragma unroll
            for (int nt = 0; nt < 16; nt++) {
                oacc[nt][j * 2]     *= corr;
                oacc[nt][j * 2 + 1] *= corr;
            }
        }
        __syncwarp();

#pragma unroll
        for (int k8 = 0; k8 < 8; k8++) {
            const int kk = k8 * 8 + tig;
            unsigned a[4];
            a[0] = sm.Ps[r0 + gid][kk];
            a[1] = sm.Ps[r0 + gid + 8][kk];
            a[2] = sm.Ps[r0 + gid][kk + 4];
            a[3] = sm.Ps[r0 + gid + 8][kk + 4];
#pragma unroll
            for (int nt = 0; nt < 16; nt++) {
                unsigned bf[2];
                bf[0] = sm.Vs[k8 * 8 + tig][nt * 8 + gid];
                bf[1] = sm.Vs[k8 * 8 + tig + 4][nt * 8 + gid];
                mma_tf32(oacc[nt], a, bf);
            }
        }
    }

#pragma unroll
    for (int j = 0; j < 2; j++) {
        const float inv = (l_i[j] > 0.0f) ? (1.0f / l_i[j]) : 0.0f;
        const size_t orow = (size_t)(b * 512 + qt * 128 + r0 + gid + j * 8);
        float* op = out + orow * 2048 + h * 128 + tig * 2;
#pragma unroll
        for (int nt = 0; nt < 16; nt++) {
            float2 o;
            o.x = oacc[nt][j * 2]     * inv;
            o.y = oacc[nt][j * 2 + 1] * inv;
            *(float2*)(op + nt * 8) = o;
        }
    }
}

// ============================================================================
extern "C" void kernel_launch(void* const* d_in, const int* in_sizes, int n_in,
                              void* d_out, int out_size)
{
    (void)in_sizes; (void)n_in; (void)out_size;
    const float* v     = (const float*)d_in[0];
    const float* q     = (const float*)d_in[1];
    const float* vmask = (const float*)d_in[2];
    const float* qmask = (const float*)d_in[3];
    const float* Wv    = (const float*)d_in[4];
    const float* bv    = (const float*)d_in[5];
    const float* Wq    = (const float*)d_in[6];
    const float* bq    = (const float*)d_in[7];
    const float* Wvo   = (const float*)d_in[8];
    const float* bvo   = (const float*)d_in[9];
    const float* Wqo   = (const float*)d_in[10];
    const float* bqo   = (const float*)d_in[11];

    float* out_v = (float*)d_out;
    float* out_q = out_v + (size_t)ROWS * OS_W;

    float *vtrans, *qtrans, *vupd, *qupd;
    cudaGetSymbolAddress((void**)&vtrans, g_vtrans);
    cudaGetSymbolAddress((void**)&qtrans, g_qtrans);
    cudaGetSymbolAddress((void**)&vupd,   g_vupd);
    cudaGetSymbolAddress((void**)&qupd,   g_qupd);

    cudaFuncSetAttribute(attn_mma_kernel, cudaFuncAttributeMaxDynamicSharedMemorySize,
                         (int)sizeof(AttnSmem2));

    dim3 blk(256);

    // 1) v_trans = relu(v @ Wv + bv) * v_mask     [8192,6144] K=2048
    mma_gemm_kernel<<<dim3(TRANS_W / BN, ROWS / BM), blk>>>(
        v, 2048, nullptr, 0, Wv, vtrans, bv, vmask, TRANS_W);
    // 2) q_trans = relu(q @ Wq + bq) * q_mask     [8192,6144] K=1024
    mma_gemm_kernel<<<dim3(TRANS_W / BN, ROWS / BM), blk>>>(
        q, 1024, nullptr, 0, Wq, qtrans, bq, qmask, TRANS_W);

    // 3) q2v attention -> v_update
    attn_mma_kernel<<<dim3(4, 16, 16), blk, sizeof(AttnSmem2)>>>(vtrans, qtrans, qmask, vupd);
    // 4) v2q attention -> q_update
    attn_mma_kernel<<<dim3(4, 16, 16), blk, sizeof(AttnSmem2)>>>(qtrans, vtrans, vmask, qupd);

    // 5) updated_v = relu([v | v_update] @ Wvo + bvo)   (fused concat GEMM)
    mma_gemm_kernel<<<dim3(OS_W / BN, ROWS / BM), blk>>>(
        v, 2048, vupd, 2048, Wvo, out_v, bvo, nullptr, OS_W);
    // 6) updated_q = relu([q | q_update] @ Wqo + bqo)
    mma_gemm_kernel<<<dim3(OS_W / BN, ROWS / BM), blk>>>(
        q, 1024, qupd, 2048, Wqo, out_q, bqo, nullptr, OS_W);
}

// round 7
// speedup vs baseline: 1.5198x; 1.4307x over previous
#include <cuda_runtime.h>
#include <cuda_fp16.h>
#include <math.h>

// Problem constants
// B=16, N=M=512, VS=2048, QS=1024, OS=2048, H=16, DH=128
#define ROWS      8192        // B * 512
#define TRANS_W   6144        // 3 * OS
#define OS_W      2048

// -------------------- scratch (device globals; no allocations allowed) -----
__device__ float g_vtrans[(size_t)ROWS * TRANS_W];
__device__ float g_qtrans[(size_t)ROWS * TRANS_W];
__device__ float g_vupd  [(size_t)ROWS * OS_W];
__device__ float g_qupd  [(size_t)ROWS * OS_W];

__device__ __forceinline__ unsigned f2tf32(float x) {
    unsigned r;
    asm("cvt.rna.tf32.f32 %0, %1;" : "=r"(r) : "f"(x));
    return r;
}

__device__ __forceinline__ unsigned pack_h2(float lo, float hi) {
    __half2 h = __floats2half2_rn(lo, hi);
    return *(unsigned*)&h;
}

// fp16 MMA, fp32 accumulate: D[16x8] += A[16x16] * B[16x8]
__device__ __forceinline__ void mma_f16(float c[4], const unsigned a[4], const unsigned b[2]) {
    asm volatile(
        "mma.sync.aligned.m16n8k16.row.col.f32.f16.f16.f32 "
        "{%0,%1,%2,%3}, {%4,%5,%6,%7}, {%8,%9}, {%0,%1,%2,%3};\n"
        : "+f"(c[0]), "+f"(c[1]), "+f"(c[2]), "+f"(c[3])
        : "r"(a[0]), "r"(a[1]), "r"(a[2]), "r"(a[3]),
          "r"(b[0]), "r"(b[1]));
}

__device__ __forceinline__ void mma_tf32(float c[4], const unsigned a[4], const unsigned b[2]) {
    asm volatile(
        "mma.sync.aligned.m16n8k8.row.col.f32.tf32.tf32.f32 "
        "{%0,%1,%2,%3}, {%4,%5,%6,%7}, {%8,%9}, {%0,%1,%2,%3};\n"
        : "+f"(c[0]), "+f"(c[1]), "+f"(c[2]), "+f"(c[3])
        : "r"(a[0]), "r"(a[1]), "r"(a[2]), "r"(a[3]),
          "r"(b[0]), "r"(b[1]));
}

// ============================================================================
// FP16 tensor-core GEMM (fp32 accum), CTA 128x128, warp 64x32, BK=16,
// double-buffered, dual-A concat (rows from A1 for k<K1, A2 beyond).
// C = relu(concat(A1,A2)@B + bias[col]) * mask[row]   (mask optional)
// SMEM holds fp16x2 pairs along k:
//   As[m][p]  p=k/2 (8 pairs, stride 12)  -> a-frag LDS conflict-free
//   Bs[p][n]  (8 pair-rows, stride 136)   -> b-frag LDS conflict-free
// ============================================================================
#define BM 128
#define BN 128
#define BK 16
#define ASTRIDE 12
#define BSTRIDE 136

__global__ void __launch_bounds__(256, 2)
hgemm_kernel(const float* __restrict__ A1, int K1,
             const float* __restrict__ A2, int K2,
             const float* __restrict__ Bm,
             float* __restrict__ C,
             const float* __restrict__ bias, const float* __restrict__ mask,
             int N)
{
    __shared__ unsigned As[2][BM][ASTRIDE];
    __shared__ unsigned Bs[2][8][BSTRIDE];

    const int tid  = threadIdx.x;
    const int lane = tid & 31;
    const int warp = tid >> 5;
    const int gid  = lane >> 2;        // 0..7
    const int tig  = lane & 3;         // 0..3
    const int wm = (warp >> 2) * 64;   // 0 or 64
    const int wn = (warp & 3) * 32;    // 0,32,64,96

    const int rowBase = blockIdx.y * BM;
    const int colBase = blockIdx.x * BN;

    // A staging: thread loads float4 at rows aR0, aR0+64, k-offset aK0
    const int aR0 = tid >> 2;              // 0..63
    const int aK0 = (tid & 3) << 2;        // 0/4/8/12
    const int aR1 = aR0 + 64;
    // B staging: thread loads rows (2*pr, 2*pr+1), 4 cols
    const int pr  = tid >> 5;              // 0..7 pair-row
    const int c0  = (tid & 31) << 2;       // 0..124

    const int K = K1 + K2;
    const int kChunks = K / BK;

    // precomputed per-row base pointers; per-chunk cost = 1 select + add
    const float* P1r0 = (K1 > 0) ? A1 + (size_t)(rowBase + aR0) * K1 : nullptr;
    const float* P1r1 = (K1 > 0) ? A1 + (size_t)(rowBase + aR1) * K1 : nullptr;
    const float* P2r0 = (K2 > 0) ? A2 + (size_t)(rowBase + aR0) * K2 - K1 : nullptr;
    const float* P2r1 = (K2 > 0) ? A2 + (size_t)(rowBase + aR1) * K2 - K1 : nullptr;

    const float* Blo = Bm + (size_t)(2 * pr)     * N + colBase + c0;
    const float* Bhi = Bm + (size_t)(2 * pr + 1) * N + colBase + c0;

    float acc[4][4][4];
#pragma unroll
    for (int i = 0; i < 4; i++)
#pragma unroll
        for (int j = 0; j < 4; j++)
#pragma unroll
            for (int r = 0; r < 4; r++) acc[i][j][r] = 0.0f;

    // ---- prologue: prefetch chunk 0 ----
    float4 ra0, ra1, rblo, rbhi;
    {
        const float* s0 = (0 < K1) ? P1r0 : P2r0;
        const float* s1 = (0 < K1) ? P1r1 : P2r1;
        ra0 = *(const float4*)(s0 + aK0);
        ra1 = *(const float4*)(s1 + aK0);
        rblo = *(const float4*)Blo;
        rbhi = *(const float4*)Bhi;
    }

    for (int ck = 0; ck < kChunks; ck++) {
        const int cur = ck & 1;

        // A: pack k-pairs (x,y),(z,w) -> 2 uints per row
        {
            uint2 u0 = { pack_h2(ra0.x, ra0.y), pack_h2(ra0.z, ra0.w) };
            uint2 u1 = { pack_h2(ra1.x, ra1.y), pack_h2(ra1.z, ra1.w) };
            *(uint2*)&As[cur][aR0][aK0 >> 1] = u0;
            *(uint2*)&As[cur][aR1][aK0 >> 1] = u1;
        }
        // B: pack (k even, k odd) pairs per column -> 4 uints
        {
            uint4 u;
            u.x = pack_h2(rblo.x, rbhi.x);
            u.y = pack_h2(rblo.y, rbhi.y);
            u.z = pack_h2(rblo.z, rbhi.z);
            u.w = pack_h2(rblo.w, rbhi.w);
            *(uint4*)&Bs[cur][pr][c0] = u;
        }
        __syncthreads();

        // prefetch next chunk
        if (ck + 1 < kChunks) {
            const int k0n = (ck + 1) * BK;
            const float* s0 = (k0n < K1) ? P1r0 : P2r0;
            const float* s1 = (k0n < K1) ? P1r1 : P2r1;
            ra0 = *(const float4*)(s0 + k0n + aK0);
            ra1 = *(const float4*)(s1 + k0n + aK0);
            rblo = *(const float4*)(Blo + (size_t)k0n * N);
            rbhi = *(const float4*)(Bhi + (size_t)k0n * N);
        }

        // compute: one k16 step = 16 MMAs
        unsigned afr[4][4];
#pragma unroll
        for (int mt = 0; mt < 4; mt++) {
            const int r = wm + mt * 16 + gid;
            afr[mt][0] = As[cur][r][tig];
            afr[mt][1] = As[cur][r + 8][tig];
            afr[mt][2] = As[cur][r][tig + 4];
            afr[mt][3] = As[cur][r + 8][tig + 4];
        }
        unsigned bfr[4][2];
#pragma unroll
        for (int nt = 0; nt < 4; nt++) {
            const int c = wn + nt * 8 + gid;
            bfr[nt][0] = Bs[cur][tig][c];
            bfr[nt][1] = Bs[cur][tig + 4][c];
        }
#pragma unroll
        for (int mt = 0; mt < 4; mt++)
#pragma unroll
            for (int nt = 0; nt < 4; nt++)
                mma_f16(acc[mt][nt], afr[mt], bfr[nt]);
        // single sync per chunk: next store targets the other stage
    }

    // ---- epilogue: relu(x + bias[col]) * mask[row] ----
#pragma unroll
    for (int mt = 0; mt < 4; mt++) {
        const int r0 = rowBase + wm + mt * 16 + gid;
        const int r1 = r0 + 8;
        const float m0 = mask ? mask[r0] : 1.0f;
        const float m1 = mask ? mask[r1] : 1.0f;
#pragma unroll
        for (int nt = 0; nt < 4; nt++) {
            const int c = colBase + wn + nt * 8 + (tig << 1);
            const float b0 = bias[c], b1 = bias[c + 1];
            float2 v0, v1;
            v0.x = fmaxf(acc[mt][nt][0] + b0, 0.0f) * m0;
            v0.y = fmaxf(acc[mt][nt][1] + b1, 0.0f) * m0;
            v1.x = fmaxf(acc[mt][nt][2] + b0, 0.0f) * m1;
            v1.y = fmaxf(acc[mt][nt][3] + b1, 0.0f) * m1;
            *(float2*)(C + (size_t)r0 * N + c) = v0;
            *(float2*)(C + (size_t)r1 * N + c) = v1;
        }
    }
}

// ============================================================================
// TF32 tensor-core flash attention (unchanged from R4, passing).
// ============================================================================
struct AttnSmem2 {
    unsigned Qs[128][132];
    unsigned Ks[64][132];
    unsigned Vs[64][136];
    unsigned Ps[128][68];
    float    Mk[64];
};

__global__ void __launch_bounds__(256)
attn_mma_kernel(const float* __restrict__ Tq, const float* __restrict__ Tk,
                const float* __restrict__ maskK, float* __restrict__ out)
{
    extern __shared__ char smem_raw[];
    AttnSmem2& sm = *reinterpret_cast<AttnSmem2*>(smem_raw);

    const int b  = blockIdx.z;
    const int h  = blockIdx.y;
    const int qt = blockIdx.x;
    const int tid  = threadIdx.x;
    const int lane = tid & 31;
    const int warp = tid >> 5;
    const int r0   = warp * 16;
    const int gid  = lane >> 2;
    const int tig  = lane & 3;
    const float SCALE = 0.08838834764831845f;

    const float* qbase = Tq + (size_t)(b * 512 + qt * 128) * 6144 + 2048 + h * 128;
#pragma unroll
    for (int it = 0; it < 16; it++) {
        int lin = it * 256 + tid;
        int r = lin >> 5, c4 = (lin & 31) << 2;
        float4 v = *(const float4*)(qbase + (size_t)r * 6144 + c4);
        uint4 u = { f2tf32(v.x), f2tf32(v.y), f2tf32(v.z), f2tf32(v.w) };
        *(uint4*)&sm.Qs[r][c4] = u;
    }

    float m_i[2] = { -INFINITY, -INFINITY };
    float l_i[2] = { 0.0f, 0.0f };
    float oacc[16][4];
#pragma unroll
    for (int nt = 0; nt < 16; nt++)
#pragma unroll
        for (int j = 0; j < 4; j++) oacc[nt][j] = 0.0f;

    const float* kbase = Tk + (size_t)b * 512 * 6144 + h * 128;
    const float* vbase = kbase + 4096;

    for (int kt = 0; kt < 8; kt++) {
        __syncthreads();
#pragma unroll
        for (int it = 0; it < 8; it++) {
            int lin = it * 256 + tid;
            int r = lin >> 5, c4 = (lin & 31) << 2;
            float4 kv = *(const float4*)(kbase + (size_t)(kt * 64 + r) * 6144 + c4);
            uint4 ku = { f2tf32(kv.x), f2tf32(kv.y), f2tf32(kv.z), f2tf32(kv.w) };
            *(uint4*)&sm.Ks[r][c4] = ku;
            float4 vv = *(const float4*)(vbase + (size_t)(kt * 64 + r) * 6144 + c4);
            uint4 vu = { f2tf32(vv.x), f2tf32(vv.y), f2tf32(vv.z), f2tf32(vv.w) };
            *(uint4*)&sm.Vs[r][c4] = vu;
        }
        if (tid < 64) sm.Mk[tid] = maskK[b * 512 + kt * 64 + tid];
        __syncthreads();

        float c[8][4];
#pragma unroll
        for (int nt = 0; nt < 8; nt++)
#pragma unroll
            for (int j = 0; j < 4; j++) c[nt][j] = 0.0f;

#pragma unroll
        for (int k8 = 0; k8 < 16; k8++) {
            const int kk = k8 * 8 + tig;
            unsigned a[4];
            a[0] = sm.Qs[r0 + gid][kk];
            a[1] = sm.Qs[r0 + gid + 8][kk];
            a[2] = sm.Qs[r0 + gid][kk + 4];
            a[3] = sm.Qs[r0 + gid + 8][kk + 4];
#pragma unroll
            for (int nt = 0; nt < 8; nt++) {
                unsigned bf[2];
                bf[0] = sm.Ks[nt * 8 + gid][kk];
                bf[1] = sm.Ks[nt * 8 + gid][kk + 4];
                mma_tf32(c[nt], a, bf);
            }
        }

#pragma unroll
        for (int nt = 0; nt < 8; nt++) {
            const int col = nt * 8 + tig * 2;
            const float k0m = sm.Mk[col];
            const float k1m = sm.Mk[col + 1];
            c[nt][0] = (k0m != 0.0f) ? c[nt][0] * SCALE : -INFINITY;
            c[nt][1] = (k1m != 0.0f) ? c[nt][1] * SCALE : -INFINITY;
            c[nt][2] = (k0m != 0.0f) ? c[nt][2] * SCALE : -INFINITY;
            c[nt][3] = (k1m != 0.0f) ? c[nt][3] * SCALE : -INFINITY;
        }

#pragma unroll
        for (int j = 0; j < 2; j++) {
            float tmax = -INFINITY;
#pragma unroll
            for (int nt = 0; nt < 8; nt++)
                tmax = fmaxf(tmax, fmaxf(c[nt][j * 2], c[nt][j * 2 + 1]));
            tmax = fmaxf(tmax, __shfl_xor_sync(0xffffffffu, tmax, 1));
            tmax = fmaxf(tmax, __shfl_xor_sync(0xffffffffu, tmax, 2));
            float mnew  = fmaxf(m_i[j], tmax);
            float msafe = (mnew == -INFINITY) ? 0.0f : mnew;
            float corr  = __expf(m_i[j] - msafe);
            float lsum = 0.0f;
            const int row = r0 + gid + j * 8;
#pragma unroll
            for (int nt = 0; nt < 8; nt++) {
                float p0 = __expf(c[nt][j * 2]     - msafe);
                float p1 = __expf(c[nt][j * 2 + 1] - msafe);
                lsum += p0 + p1;
                uint2 pu = { f2tf32(p0), f2tf32(p1) };
                *(uint2*)&sm.Ps[row][nt * 8 + tig * 2] = pu;
            }
            lsum += __shfl_xor_sync(0xffffffffu, lsum, 1);
            lsum += __shfl_xor_sync(0xffffffffu, lsum, 2);
            l_i[j] = l_i[j] * corr + lsum;
            m_i[j] = mnew;
#pragma unroll
            for (int nt = 0; nt < 16; nt++) {
                oacc[nt][j * 2]     *= corr;
                oacc[nt][j * 2 + 1] *= corr;
            }
        }
        __syncwarp();

#pragma unroll
        for (int k8 = 0; k8 < 8; k8++) {
            const int kk = k8 * 8 + tig;
            unsigned a[4];
            a[0] = sm.Ps[r0 + gid][kk];
            a[1] = sm.Ps[r0 + gid + 8][kk];
            a[2] = sm.Ps[r0 + gid][kk + 4];
            a[3] = sm.Ps[r0 + gid + 8][kk + 4];
#pragma unroll
            for (int nt = 0; nt < 16; nt++) {
                unsigned bf[2];
                bf[0] = sm.Vs[k8 * 8 + tig][nt * 8 + gid];
                bf[1] = sm.Vs[k8 * 8 + tig + 4][nt * 8 + gid];
                mma_tf32(oacc[nt], a, bf);
            }
        }
    }

#pragma unroll
    for (int j = 0; j < 2; j++) {
        const float inv = (l_i[j] > 0.0f) ? (1.0f / l_i[j]) : 0.0f;
        const size_t orow = (size_t)(b * 512 + qt * 128 + r0 + gid + j * 8);
        float* op = out + orow * 2048 + h * 128 + tig * 2;
#pragma unroll
        for (int nt = 0; nt < 16; nt++) {
            float2 o;
            o.x = oacc[nt][j * 2]     * inv;
            o.y = oacc[nt][j * 2 + 1] * inv;
            *(float2*)(op + nt * 8) = o;
        }
    }
}

// ============================================================================
extern "C" void kernel_launch(void* const* d_in, const int* in_sizes, int n_in,
                              void* d_out, int out_size)
{
    (void)in_sizes; (void)n_in; (void)out_size;
    const float* v     = (const float*)d_in[0];
    const float* q     = (const float*)d_in[1];
    const float* vmask = (const float*)d_in[2];
    const float* qmask = (const float*)d_in[3];
    const float* Wv    = (const float*)d_in[4];
    const float* bv    = (const float*)d_in[5];
    const float* Wq    = (const float*)d_in[6];
    const float* bq    = (const float*)d_in[7];
    const float* Wvo   = (const float*)d_in[8];
    const float* bvo   = (const float*)d_in[9];
    const float* Wqo   = (const float*)d_in[10];
    const float* bqo   = (const float*)d_in[11];

    float* out_v = (float*)d_out;
    float* out_q = out_v + (size_t)ROWS * OS_W;

    float *vtrans, *qtrans, *vupd, *qupd;
    cudaGetSymbolAddress((void**)&vtrans, g_vtrans);
    cudaGetSymbolAddress((void**)&qtrans, g_qtrans);
    cudaGetSymbolAddress((void**)&vupd,   g_vupd);
    cudaGetSymbolAddress((void**)&qupd,   g_qupd);

    cudaFuncSetAttribute(attn_mma_kernel, cudaFuncAttributeMaxDynamicSharedMemorySize,
                         (int)sizeof(AttnSmem2));

    dim3 blk(256);

    // 1) v_trans = relu(v @ Wv + bv) * v_mask     [8192,6144] K=2048
    hgemm_kernel<<<dim3(TRANS_W / BN, ROWS / BM), blk>>>(
        v, 2048, nullptr, 0, Wv, vtrans, bv, vmask, TRANS_W);
    // 2) q_trans = relu(q @ Wq + bq) * q_mask     [8192,6144] K=1024
    hgemm_kernel<<<dim3(TRANS_W / BN, ROWS / BM), blk>>>(
        q, 1024, nullptr, 0, Wq, qtrans, bq, qmask, TRANS_W);

    // 3) q2v attention -> v_update
    attn_mma_kernel<<<dim3(4, 16, 16), blk, sizeof(AttnSmem2)>>>(vtrans, qtrans, qmask, vupd);
    // 4) v2q attention -> q_update
    attn_mma_kernel<<<dim3(4, 16, 16), blk, sizeof(AttnSmem2)>>>(qtrans, vtrans, vmask, qupd);

    // 5) updated_v = relu([v | v_update] @ Wvo + bvo)   (fused concat GEMM)
    hgemm_kernel<<<dim3(OS_W / BN, ROWS / BM), blk>>>(
        v, 2048, vupd, 2048, Wvo, out_v, bvo, nullptr, OS_W);
    // 6) updated_q = relu([q | q_update] @ Wqo + bqo)
    hgemm_kernel<<<dim3(OS_W / BN, ROWS / BM), blk>>>(
        q, 1024, qupd, 2048, Wqo, out_q, bqo, nullptr, OS_W);
}

// round 8
// speedup vs baseline: 1.6258x; 1.0698x over previous
#include <cuda_runtime.h>
#include <cuda_fp16.h>
#include <math.h>

// Problem constants
// B=16, N=M=512, VS=2048, QS=1024, OS=2048, H=16, DH=128
#define ROWS      8192        // B * 512
#define TRANS_W   6144        // 3 * OS
#define OS_W      2048

// -------------------- scratch (device globals; no allocations allowed) -----
__device__ float g_vtrans[(size_t)ROWS * TRANS_W];
__device__ float g_qtrans[(size_t)ROWS * TRANS_W];
__device__ float g_vupd  [(size_t)ROWS * OS_W];
__device__ float g_qupd  [(size_t)ROWS * OS_W];

__device__ __forceinline__ unsigned pack_h2(float lo, float hi) {
    __half2 h = __floats2half2_rn(lo, hi);
    return *(unsigned*)&h;
}

// fp16 MMA, fp32 accumulate: D[16x8] += A[16x16] * B[16x8]
__device__ __forceinline__ void mma_f16(float c[4], const unsigned a[4], const unsigned b[2]) {
    asm volatile(
        "mma.sync.aligned.m16n8k16.row.col.f32.f16.f16.f32 "
        "{%0,%1,%2,%3}, {%4,%5,%6,%7}, {%8,%9}, {%0,%1,%2,%3};\n"
        : "+f"(c[0]), "+f"(c[1]), "+f"(c[2]), "+f"(c[3])
        : "r"(a[0]), "r"(a[1]), "r"(a[2]), "r"(a[3]),
          "r"(b[0]), "r"(b[1]));
}

// ============================================================================
// FP16 tensor-core GEMM (fp32 accum) — unchanged from R7 (passing).
// ============================================================================
#define BM 128
#define BN 128
#define BK 16
#define ASTRIDE 12
#define BSTRIDE 136

__global__ void __launch_bounds__(256, 2)
hgemm_kernel(const float* __restrict__ A1, int K1,
             const float* __restrict__ A2, int K2,
             const float* __restrict__ Bm,
             float* __restrict__ C,
             const float* __restrict__ bias, const float* __restrict__ mask,
             int N)
{
    __shared__ unsigned As[2][BM][ASTRIDE];
    __shared__ unsigned Bs[2][8][BSTRIDE];

    const int tid  = threadIdx.x;
    const int lane = tid & 31;
    const int warp = tid >> 5;
    const int gid  = lane >> 2;
    const int tig  = lane & 3;
    const int wm = (warp >> 2) * 64;
    const int wn = (warp & 3) * 32;

    const int rowBase = blockIdx.y * BM;
    const int colBase = blockIdx.x * BN;

    const int aR0 = tid >> 2;
    const int aK0 = (tid & 3) << 2;
    const int aR1 = aR0 + 64;
    const int pr  = tid >> 5;
    const int c0  = (tid & 31) << 2;

    const int K = K1 + K2;
    const int kChunks = K / BK;

    const float* P1r0 = (K1 > 0) ? A1 + (size_t)(rowBase + aR0) * K1 : nullptr;
    const float* P1r1 = (K1 > 0) ? A1 + (size_t)(rowBase + aR1) * K1 : nullptr;
    const float* P2r0 = (K2 > 0) ? A2 + (size_t)(rowBase + aR0) * K2 - K1 : nullptr;
    const float* P2r1 = (K2 > 0) ? A2 + (size_t)(rowBase + aR1) * K2 - K1 : nullptr;

    const float* Blo = Bm + (size_t)(2 * pr)     * N + colBase + c0;
    const float* Bhi = Bm + (size_t)(2 * pr + 1) * N + colBase + c0;

    float acc[4][4][4];
#pragma unroll
    for (int i = 0; i < 4; i++)
#pragma unroll
        for (int j = 0; j < 4; j++)
#pragma unroll
            for (int r = 0; r < 4; r++) acc[i][j][r] = 0.0f;

    float4 ra0, ra1, rblo, rbhi;
    {
        const float* s0 = (0 < K1) ? P1r0 : P2r0;
        const float* s1 = (0 < K1) ? P1r1 : P2r1;
        ra0 = *(const float4*)(s0 + aK0);
        ra1 = *(const float4*)(s1 + aK0);
        rblo = *(const float4*)Blo;
        rbhi = *(const float4*)Bhi;
    }

    for (int ck = 0; ck < kChunks; ck++) {
        const int cur = ck & 1;

        {
            uint2 u0 = { pack_h2(ra0.x, ra0.y), pack_h2(ra0.z, ra0.w) };
            uint2 u1 = { pack_h2(ra1.x, ra1.y), pack_h2(ra1.z, ra1.w) };
            *(uint2*)&As[cur][aR0][aK0 >> 1] = u0;
            *(uint2*)&As[cur][aR1][aK0 >> 1] = u1;
        }
        {
            uint4 u;
            u.x = pack_h2(rblo.x, rbhi.x);
            u.y = pack_h2(rblo.y, rbhi.y);
            u.z = pack_h2(rblo.z, rbhi.z);
            u.w = pack_h2(rblo.w, rbhi.w);
            *(uint4*)&Bs[cur][pr][c0] = u;
        }
        __syncthreads();

        if (ck + 1 < kChunks) {
            const int k0n = (ck + 1) * BK;
            const float* s0 = (k0n < K1) ? P1r0 : P2r0;
            const float* s1 = (k0n < K1) ? P1r1 : P2r1;
            ra0 = *(const float4*)(s0 + k0n + aK0);
            ra1 = *(const float4*)(s1 + k0n + aK0);
            rblo = *(const float4*)(Blo + (size_t)k0n * N);
            rbhi = *(const float4*)(Bhi + (size_t)k0n * N);
        }

        unsigned afr[4][4];
#pragma unroll
        for (int mt = 0; mt < 4; mt++) {
            const int r = wm + mt * 16 + gid;
            afr[mt][0] = As[cur][r][tig];
            afr[mt][1] = As[cur][r + 8][tig];
            afr[mt][2] = As[cur][r][tig + 4];
            afr[mt][3] = As[cur][r + 8][tig + 4];
        }
        unsigned bfr[4][2];
#pragma unroll
        for (int nt = 0; nt < 4; nt++) {
            const int c = wn + nt * 8 + gid;
            bfr[nt][0] = Bs[cur][tig][c];
            bfr[nt][1] = Bs[cur][tig + 4][c];
        }
#pragma unroll
        for (int mt = 0; mt < 4; mt++)
#pragma unroll
            for (int nt = 0; nt < 4; nt++)
                mma_f16(acc[mt][nt], afr[mt], bfr[nt]);
    }

#pragma unroll
    for (int mt = 0; mt < 4; mt++) {
        const int r0 = rowBase + wm + mt * 16 + gid;
        const int r1 = r0 + 8;
        const float m0 = mask ? mask[r0] : 1.0f;
        const float m1 = mask ? mask[r1] : 1.0f;
#pragma unroll
        for (int nt = 0; nt < 4; nt++) {
            const int c = colBase + wn + nt * 8 + (tig << 1);
            const float b0 = bias[c], b1 = bias[c + 1];
            float2 v0, v1;
            v0.x = fmaxf(acc[mt][nt][0] + b0, 0.0f) * m0;
            v0.y = fmaxf(acc[mt][nt][1] + b1, 0.0f) * m0;
            v1.x = fmaxf(acc[mt][nt][2] + b0, 0.0f) * m1;
            v1.y = fmaxf(acc[mt][nt][3] + b1, 0.0f) * m1;
            *(float2*)(C + (size_t)r0 * N + c) = v0;
            *(float2*)(C + (size_t)r1 * N + c) = v1;
        }
    }
}

// ============================================================================
// FP16 tensor-core flash attention (fp32 accum, fp32 softmax).
// Same structure as R4/R7 attention, but all tiles are packed fp16 pairs and
// both MMAs are m16n8k16 — half the MMA and LDS count of the tf32 version.
//   Qh[q][pd]   pairs along d, stride 68  (d=128 -> 64 pairs)
//   Kh[k][pd]   pairs along d, stride 68
//   Vh[pk][n]   pairs along k, stride 136 (64 keys -> 32 pair-rows)
//   Ps[q][pk]   pairs along key, stride 36
// ============================================================================
struct AttnSmem3 {
    unsigned Qh[128][68];
    unsigned Kh[64][68];
    unsigned Vh[32][136];
    unsigned Ps[128][36];
    float    Mk[64];
};

__global__ void __launch_bounds__(256)
attn_mma_kernel(const float* __restrict__ Tq, const float* __restrict__ Tk,
                const float* __restrict__ maskK, float* __restrict__ out)
{
    extern __shared__ char smem_raw[];
    AttnSmem3& sm = *reinterpret_cast<AttnSmem3*>(smem_raw);

    const int b  = blockIdx.z;
    const int h  = blockIdx.y;
    const int qt = blockIdx.x;     // 0..3, 128 query rows each
    const int tid  = threadIdx.x;
    const int lane = tid & 31;
    const int warp = tid >> 5;
    const int r0   = warp * 16;    // query rows owned by this warp
    const int gid  = lane >> 2;    // 0..7
    const int tig  = lane & 3;     // 0..3
    const float SCALE = 0.08838834764831845f;  // 1/sqrt(128)

    // ---- load Q tile [128 x 128] -> fp16-pair smem ----
    const float* qbase = Tq + (size_t)(b * 512 + qt * 128) * 6144 + 2048 + h * 128;
#pragma unroll
    for (int it = 0; it < 16; it++) {
        int lin = it * 256 + tid;
        int r = lin >> 5, c4 = (lin & 31) << 2;
        float4 v = *(const float4*)(qbase + (size_t)r * 6144 + c4);
        uint2 u = { pack_h2(v.x, v.y), pack_h2(v.z, v.w) };
        *(uint2*)&sm.Qh[r][c4 >> 1] = u;
    }

    float m_i[2] = { -INFINITY, -INFINITY };
    float l_i[2] = { 0.0f, 0.0f };
    float oacc[16][4];
#pragma unroll
    for (int nt = 0; nt < 16; nt++)
#pragma unroll
        for (int j = 0; j < 4; j++) oacc[nt][j] = 0.0f;

    const float* kbase = Tk + (size_t)b * 512 * 6144 + h * 128;   // keys
    const float* vbase = kbase + 4096;                             // vals

    const int vpr = tid >> 5;          // V staging pair-row base (warp id)
    const int vc0 = (tid & 31) << 2;   // V staging col

    for (int kt = 0; kt < 8; kt++) {
        __syncthreads();   // WAR on Kh/Vh/Ps across warps

        // K: pairs along d
#pragma unroll
        for (int it = 0; it < 8; it++) {
            int lin = it * 256 + tid;
            int r = lin >> 5, c4 = (lin & 31) << 2;
            float4 kv = *(const float4*)(kbase + (size_t)(kt * 64 + r) * 6144 + c4);
            uint2 u = { pack_h2(kv.x, kv.y), pack_h2(kv.z, kv.w) };
            *(uint2*)&sm.Kh[r][c4 >> 1] = u;
        }
        // V: pairs along k (two source rows per pair-row)
#pragma unroll
        for (int it = 0; it < 4; it++) {
            int p = it * 8 + vpr;      // 0..31
            const float* vlo = vbase + (size_t)(kt * 64 + 2 * p)     * 6144 + vc0;
            const float* vhi = vbase + (size_t)(kt * 64 + 2 * p + 1) * 6144 + vc0;
            float4 lo = *(const float4*)vlo;
            float4 hi = *(const float4*)vhi;
            uint4 u;
            u.x = pack_h2(lo.x, hi.x);
            u.y = pack_h2(lo.y, hi.y);
            u.z = pack_h2(lo.z, hi.z);
            u.w = pack_h2(lo.w, hi.w);
            *(uint4*)&sm.Vh[p][vc0] = u;
        }
        if (tid < 64) sm.Mk[tid] = maskK[b * 512 + kt * 64 + tid];
        __syncthreads();

        // ---- scores: S[16 x 64] over d=128, 8 k16-steps ----
        float c[8][4];
#pragma unroll
        for (int nt = 0; nt < 8; nt++)
#pragma unroll
            for (int j = 0; j < 4; j++) c[nt][j] = 0.0f;

#pragma unroll
        for (int ks = 0; ks < 8; ks++) {
            const int pd = ks * 8 + tig;
            unsigned a[4];
            a[0] = sm.Qh[r0 + gid][pd];
            a[1] = sm.Qh[r0 + gid + 8][pd];
            a[2] = sm.Qh[r0 + gid][pd + 4];
            a[3] = sm.Qh[r0 + gid + 8][pd + 4];
#pragma unroll
            for (int nt = 0; nt < 8; nt++) {
                unsigned bf[2];
                bf[0] = sm.Kh[nt * 8 + gid][pd];
                bf[1] = sm.Kh[nt * 8 + gid][pd + 4];
                mma_f16(c[nt], a, bf);
            }
        }

        // ---- mask + scale ----
#pragma unroll
        for (int nt = 0; nt < 8; nt++) {
            const int col = nt * 8 + tig * 2;
            const float k0m = sm.Mk[col];
            const float k1m = sm.Mk[col + 1];
            c[nt][0] = (k0m != 0.0f) ? c[nt][0] * SCALE : -INFINITY;
            c[nt][1] = (k1m != 0.0f) ? c[nt][1] * SCALE : -INFINITY;
            c[nt][2] = (k0m != 0.0f) ? c[nt][2] * SCALE : -INFINITY;
            c[nt][3] = (k1m != 0.0f) ? c[nt][3] * SCALE : -INFINITY;
        }

        // ---- online softmax per owned row ----
#pragma unroll
        for (int j = 0; j < 2; j++) {
            float tmax = -INFINITY;
#pragma unroll
            for (int nt = 0; nt < 8; nt++)
                tmax = fmaxf(tmax, fmaxf(c[nt][j * 2], c[nt][j * 2 + 1]));
            tmax = fmaxf(tmax, __shfl_xor_sync(0xffffffffu, tmax, 1));
            tmax = fmaxf(tmax, __shfl_xor_sync(0xffffffffu, tmax, 2));
            float mnew  = fmaxf(m_i[j], tmax);
            float msafe = (mnew == -INFINITY) ? 0.0f : mnew;
            float corr  = __expf(m_i[j] - msafe);
            float lsum = 0.0f;
            const int row = r0 + gid + j * 8;
#pragma unroll
            for (int nt = 0; nt < 8; nt++) {
                float p0 = __expf(c[nt][j * 2]     - msafe);
                float p1 = __expf(c[nt][j * 2 + 1] - msafe);
                lsum += p0 + p1;
                sm.Ps[row][nt * 4 + tig] = pack_h2(p0, p1);   // key pair
            }
            lsum += __shfl_xor_sync(0xffffffffu, lsum, 1);
            lsum += __shfl_xor_sync(0xffffffffu, lsum, 2);
            l_i[j] = l_i[j] * corr + lsum;
            m_i[j] = mnew;
#pragma unroll
            for (int nt = 0; nt < 16; nt++) {
                oacc[nt][j * 2]     *= corr;
                oacc[nt][j * 2 + 1] *= corr;
            }
        }
        __syncwarp();   // Ps rows are warp-private

        // ---- PV: O[16 x 128] += P[16 x 64] @ V[64 x 128], 4 k16-steps ----
#pragma unroll
        for (int ks = 0; ks < 4; ks++) {
            const int pk = ks * 8 + tig;
            unsigned a[4];
            a[0] = sm.Ps[r0 + gid][pk];
            a[1] = sm.Ps[r0 + gid + 8][pk];
            a[2] = sm.Ps[r0 + gid][pk + 4];
            a[3] = sm.Ps[r0 + gid + 8][pk + 4];
#pragma unroll
            for (int nt = 0; nt < 16; nt++) {
                unsigned bf[2];
                bf[0] = sm.Vh[ks * 8 + tig][nt * 8 + gid];
                bf[1] = sm.Vh[ks * 8 + tig + 4][nt * 8 + gid];
                mma_f16(oacc[nt], a, bf);
            }
        }
    }

    // ---- write output ----
#pragma unroll
    for (int j = 0; j < 2; j++) {
        const float inv = (l_i[j] > 0.0f) ? (1.0f / l_i[j]) : 0.0f;
        const size_t orow = (size_t)(b * 512 + qt * 128 + r0 + gid + j * 8);
        float* op = out + orow * 2048 + h * 128 + tig * 2;
#pragma unroll
        for (int nt = 0; nt < 16; nt++) {
            float2 o;
            o.x = oacc[nt][j * 2]     * inv;
            o.y = oacc[nt][j * 2 + 1] * inv;
            *(float2*)(op + nt * 8) = o;
        }
    }
}

// ============================================================================
extern "C" void kernel_launch(void* const* d_in, const int* in_sizes, int n_in,
                              void* d_out, int out_size)
{
    (void)in_sizes; (void)n_in; (void)out_size;
    const float* v     = (const float*)d_in[0];
    const float* q     = (const float*)d_in[1];
    const float* vmask = (const float*)d_in[2];
    const float* qmask = (const float*)d_in[3];
    const float* Wv    = (const float*)d_in[4];
    const float* bv    = (const float*)d_in[5];
    const float* Wq    = (const float*)d_in[6];
    const float* bq    = (const float*)d_in[7];
    const float* Wvo   = (const float*)d_in[8];
    const float* bvo   = (const float*)d_in[9];
    const float* Wqo   = (const float*)d_in[10];
    const float* bqo   = (const float*)d_in[11];

    float* out_v = (float*)d_out;
    float* out_q = out_v + (size_t)ROWS * OS_W;

    float *vtrans, *qtrans, *vupd, *qupd;
    cudaGetSymbolAddress((void**)&vtrans, g_vtrans);
    cudaGetSymbolAddress((void**)&qtrans, g_qtrans);
    cudaGetSymbolAddress((void**)&vupd,   g_vupd);
    cudaGetSymbolAddress((void**)&qupd,   g_qupd);

    cudaFuncSetAttribute(attn_mma_kernel, cudaFuncAttributeMaxDynamicSharedMemorySize,
                         (int)sizeof(AttnSmem3));

    dim3 blk(256);

    // 1) v_trans = relu(v @ Wv + bv) * v_mask     [8192,6144] K=2048
    hgemm_kernel<<<dim3(TRANS_W / BN, ROWS / BM), blk>>>(
        v, 2048, nullptr, 0, Wv, vtrans, bv, vmask, TRANS_W);
    // 2) q_trans = relu(q @ Wq + bq) * q_mask     [8192,6144] K=1024
    hgemm_kernel<<<dim3(TRANS_W / BN, ROWS / BM), blk>>>(
        q, 1024, nullptr, 0, Wq, qtrans, bq, qmask, TRANS_W);

    // 3) q2v attention -> v_update
    attn_mma_kernel<<<dim3(4, 16, 16), blk, sizeof(AttnSmem3)>>>(vtrans, qtrans, qmask, vupd);
    // 4) v2q attention -> q_update
    attn_mma_kernel<<<dim3(4, 16, 16), blk, sizeof(AttnSmem3)>>>(qtrans, vtrans, vmask, qupd);

    // 5) updated_v = relu([v | v_update] @ Wvo + bvo)   (fused concat GEMM)
    hgemm_kernel<<<dim3(OS_W / BN, ROWS / BM), blk>>>(
        v, 2048, vupd, 2048, Wvo, out_v, bvo, nullptr, OS_W);
    // 6) updated_q = relu([q | q_update] @ Wqo + bqo)
    hgemm_kernel<<<dim3(OS_W / BN, ROWS / BM), blk>>>(
        q, 1024, qupd, 2048, Wqo, out_q, bqo, nullptr, OS_W);
}